// round 1
// baseline (speedup 1.0000x reference)
#include <cuda_runtime.h>
#include <math.h>

#define B 64
#define D 2048
#define H 1024
#define KSPLIT 4
#define KPER (D / KSPLIT)   // 512

// Output layout: ht [B*H] | ct [B*H*H] | nt [B*H] | mt [B*H]
#define OFF_HT 0
#define OFF_CT (B * H)
#define OFF_NT (OFF_CT + (size_t)B * H * H)
#define OFF_MT (OFF_NT + B * H)

// Scratch (device globals — no allocation allowed)
__device__ float g_part[KSPLIT][6][B][H];   // GEMM partials (6 MB)
__device__ float g_ft[B * H];
__device__ float g_ot[B * H];
__device__ float g_vt[B * H];
__device__ float g_kt[B * H];
__device__ float g_qt[B * H];
__device__ float g_denom[B];

// ---------------------------------------------------------------------------
// Kernel 1: fused 6-way projection GEMM, fp32.
// grid = (H/64 coltiles, 6 weights, KSPLIT), block = 256.
// Tile: 64 rows (all of B) x 64 cols, K chunk = KPER per z-slice.
// ---------------------------------------------------------------------------
__global__ void __launch_bounds__(256) gemm_kernel(
    const float* __restrict__ x,
    const float* __restrict__ W0, const float* __restrict__ W1,
    const float* __restrict__ W2, const float* __restrict__ W3,
    const float* __restrict__ W4, const float* __restrict__ W5)
{
    __shared__ float xs[64][32];   // [b][kk]
    __shared__ float ws[32][64];   // [kk][c]

    const int wi = blockIdx.y;
    const float* W = (wi == 0) ? W0 : (wi == 1) ? W1 : (wi == 2) ? W2
                   : (wi == 3) ? W3 : (wi == 4) ? W4 : W5;

    const int c0 = blockIdx.x * 64;
    const int kz = blockIdx.z;
    const int kstart = kz * KPER;

    const int lane = threadIdx.x & 31;
    const int warp = threadIdx.x >> 5;   // 8 warps; warp handles rows warp*8..+7

    float acc[8][2];
#pragma unroll
    for (int r = 0; r < 8; r++) { acc[r][0] = 0.f; acc[r][1] = 0.f; }

    for (int kc = 0; kc < KPER; kc += 32) {
        const int kbase = kstart + kc;
        __syncthreads();
        // Load xs: 64x32 floats (2048) by 256 threads, 8 each, coalesced.
#pragma unroll
        for (int i = 0; i < 8; i++) {
            int idx = threadIdx.x + i * 256;
            int r = idx >> 5, kk = idx & 31;
            xs[r][kk] = x[r * D + kbase + kk];
        }
        // Load ws: 32x64 floats (2048), coalesced 256B rows.
#pragma unroll
        for (int i = 0; i < 8; i++) {
            int idx = threadIdx.x + i * 256;
            int kk = idx >> 6, c = idx & 63;
            ws[kk][c] = W[(size_t)(kbase + kk) * H + c0 + c];
        }
        __syncthreads();
#pragma unroll
        for (int kk = 0; kk < 32; kk++) {
            float b0 = ws[kk][lane];
            float b1 = ws[kk][lane + 32];
#pragma unroll
            for (int r = 0; r < 8; r++) {
                float a = xs[warp * 8 + r][kk];
                acc[r][0] = fmaf(a, b0, acc[r][0]);
                acc[r][1] = fmaf(a, b1, acc[r][1]);
            }
        }
    }

#pragma unroll
    for (int r = 0; r < 8; r++) {
        int row = warp * 8 + r;
        g_part[kz][wi][row][c0 + lane]      = acc[r][0];
        g_part[kz][wi][row][c0 + lane + 32] = acc[r][1];
    }
}

// ---------------------------------------------------------------------------
// Kernel 2: gate math, nt/mt outputs, per-batch denom reduction.
// grid = B, block = H (1024).
// ---------------------------------------------------------------------------
__global__ void __launch_bounds__(1024) gate_kernel(
    const float* __restrict__ n_in, const float* __restrict__ m_in,
    const float* __restrict__ bi, const float* __restrict__ bf,
    const float* __restrict__ bo, const float* __restrict__ bq,
    const float* __restrict__ bk, const float* __restrict__ bv,
    float* __restrict__ out)
{
    const int b = blockIdx.x;
    const int h = threadIdx.x;
    const int idx = b * H + h;

    float s[6];
#pragma unroll
    for (int w = 0; w < 6; w++) {
        float acc = 0.f;
#pragma unroll
        for (int z = 0; z < KSPLIT; z++) acc += g_part[z][w][b][h];
        s[w] = acc;
    }
    float i_t = s[0] + bi[h];
    float f_t = s[1] + bf[h];
    float o_t = s[2] + bo[h];
    float qv  = s[3] + bq[h];
    float kv  = (s[4] + bk[h]) * 0.03125f;   // 1/sqrt(1024)
    float vv  = s[5] + bv[h];

    float ft = 1.f / (1.f + expf(-f_t));
    float ot = 1.f / (1.f + expf(-o_t));
    float mt = fmaxf(logf(ft) + m_in[idx], i_t);
    float ip = expf(i_t - mt);
    float nt = ft * n_in[idx] + ip * kv;

    g_ft[idx] = ft;
    g_ot[idx] = ot;
    g_vt[idx] = vv;
    g_kt[idx] = kv;
    g_qt[idx] = qv;
    out[OFF_NT + idx] = nt;
    out[OFF_MT + idx] = mt;

    // reduce sum(nt * qt) over h for this b
    float p = nt * qv;
    __shared__ float red[32];
#pragma unroll
    for (int o = 16; o > 0; o >>= 1) p += __shfl_xor_sync(0xffffffffu, p, o);
    if ((h & 31) == 0) red[h >> 5] = p;
    __syncthreads();
    if (h < 32) {
        float v = red[h];
#pragma unroll
        for (int o = 16; o > 0; o >>= 1) v += __shfl_xor_sync(0xffffffffu, v, o);
        if (h == 0) g_denom[b] = fmaxf(fabsf(v), 1.f);
    }
}

// ---------------------------------------------------------------------------
// Kernel 3: matrix-state update + fused h_tilde contraction.
// ct[b,i,j] = ft[b,i]*c[b,i,j] + vt[b,i]*kt[b,j]
// ht[b,i]   = ot[b,i] * (sum_j ct[b,i,j]*qt[b,j]) / denom[b]
// grid = B*H/4 (4 rows per block), block = 256 (float4 per thread per row).
// ---------------------------------------------------------------------------
__global__ void __launch_bounds__(256) update_kernel(
    const float* __restrict__ c_in, float* __restrict__ out)
{
    const int R = blockIdx.x * 4;          // 4 consecutive rows, same b (H%4==0)
    const int b = R / H;
    const int i0 = R % H;
    const int tid = threadIdx.x;
    const int j = tid * 4;

    const float4 kt4 = *(const float4*)&g_kt[b * H + j];
    const float4 qt4 = *(const float4*)&g_qt[b * H + j];

    float sums[4];
#pragma unroll
    for (int rr = 0; rr < 4; rr++) {
        const int i = i0 + rr;
        const float ft = __ldg(&g_ft[b * H + i]);
        const float vt = __ldg(&g_vt[b * H + i]);
        const size_t base = ((size_t)b * H + i) * H + j;
        float4 c4 = *(const float4*)&c_in[base];
        float4 ct;
        ct.x = fmaf(ft, c4.x, vt * kt4.x);
        ct.y = fmaf(ft, c4.y, vt * kt4.y);
        ct.z = fmaf(ft, c4.z, vt * kt4.z);
        ct.w = fmaf(ft, c4.w, vt * kt4.w);
        *(float4*)&out[OFF_CT + base] = ct;
        sums[rr] = ct.x * qt4.x + ct.y * qt4.y + ct.z * qt4.z + ct.w * qt4.w;
    }

    __shared__ float red[4][8];
    const int lane = tid & 31, warp = tid >> 5;
#pragma unroll
    for (int rr = 0; rr < 4; rr++) {
        float p = sums[rr];
#pragma unroll
        for (int o = 16; o > 0; o >>= 1) p += __shfl_xor_sync(0xffffffffu, p, o);
        if (lane == 0) red[rr][warp] = p;
    }
    __syncthreads();
    if (tid < 4) {
        float s = 0.f;
#pragma unroll
        for (int w = 0; w < 8; w++) s += red[tid][w];
        const int i = i0 + tid;
        float htl = s / g_denom[b];
        out[OFF_HT + b * H + i] = g_ot[b * H + i] * htl;
    }
}

// ---------------------------------------------------------------------------
extern "C" void kernel_launch(void* const* d_in, const int* in_sizes, int n_in,
                              void* d_out, int out_size)
{
    const float* x  = (const float*)d_in[0];
    const float* c  = (const float*)d_in[1];
    const float* n  = (const float*)d_in[2];
    const float* m  = (const float*)d_in[3];
    const float* Wi = (const float*)d_in[4];
    const float* Wf = (const float*)d_in[5];
    const float* Wo = (const float*)d_in[6];
    const float* Wq = (const float*)d_in[7];
    const float* Wk = (const float*)d_in[8];
    const float* Wv = (const float*)d_in[9];
    const float* bi = (const float*)d_in[10];
    const float* bf = (const float*)d_in[11];
    const float* bo = (const float*)d_in[12];
    const float* bq = (const float*)d_in[13];
    const float* bk = (const float*)d_in[14];
    const float* bv = (const float*)d_in[15];
    float* out = (float*)d_out;

    dim3 ggrid(H / 64, 6, KSPLIT);
    gemm_kernel<<<ggrid, 256>>>(x, Wi, Wf, Wo, Wq, Wk, Wv);
    gate_kernel<<<B, 1024>>>(n, m, bi, bf, bo, bq, bk, bv, out);
    update_kernel<<<B * H / 4, 256>>>(c, out);
}